// round 9
// baseline (speedup 1.0000x reference)
#include <cuda_runtime.h>
#include <cuda_bf16.h>
#include <math_constants.h>

// Rejection sampler for speculative decoding (vLLM-style).
// Inputs (order resolved at runtime from size signature + content probes):
//   draft_probs [NT,V] f32, target_probs [NT,V] f32, uniform_probs [NT] f32,
//   draft_token_ids [NT] i32, cu_num_draft_tokens [B] i32, bonus_token_ids [B] i32.
// Output: [B, L+1] written as FLOAT32 (harness __output__ dtype; ids exactly representable).

#define THREADS 1024
#define MAXL 64

typedef unsigned long long u64;
typedef unsigned int       u32;

__global__ __launch_bounds__(THREADS, 1)
void rejection_sample_kernel(const float* __restrict__ draft_probs,
                             const float* __restrict__ target_probs,
                             const void*  __restrict__ ntA,   // draft_ids OR uniform
                             const void*  __restrict__ ntB,   // the other one
                             const int*   __restrict__ bA,    // cu OR bonus
                             const int*   __restrict__ bB,    // the other one
                             float*       __restrict__ out,   // FLOAT output
                             int NT, int V, int L, int B)
{
    const int b   = blockIdx.x;
    const int tid = threadIdx.x;
    if (b >= B) return;

    // ---- device-side content disambiguation ----
    // Token ids: raw bits < 2^22 (V = 128000). Floats in (0,1): bits >= 0x00800000.
    const unsigned* pa = (const unsigned*)ntA;
    bool a_is_ids = true;
    #pragma unroll
    for (int i = 0; i < 4; ++i) {
        const int pi = (NT > 1) ? (int)(((long long)i * (NT - 1)) / 3) : 0;
        if (pa[pi] >= 0x00400000u) a_is_ids = false;
    }
    const int*   draft_ids     = a_is_ids ? (const int*)ntA   : (const int*)ntB;
    const float* uniform_probs = a_is_ids ? (const float*)ntB : (const float*)ntA;

    // cu is cumulative; its last element equals NT exactly.
    const int lastA = bA[B - 1], lastB = bB[B - 1];
    const int *cu, *bonus;
    if (lastA == NT && lastB != NT)      { cu = bA; bonus = bB; }
    else if (lastB == NT && lastA != NT) { cu = bB; bonus = bA; }
    else {
        cu = (bA[0] >= 0 && bA[0] <= lastA && lastA <= NT) ? bA : bB;
        bonus = (cu == bA) ? bB : bA;
    }

    __shared__ float s_tp[MAXL], s_dp[MAXL], s_u[MAXL];
    __shared__ int   s_tok[MAXL];
    __shared__ int   s_last, s_rej, s_rec;
    __shared__ u64   s_key[THREADS / 32];

    int start = (b == 0) ? 0 : cu[b - 1];
    start = max(0, min(start, NT));
    int nd = cu[b] - start;
    nd = max(0, min(nd, NT - start));
    const int ndc = min(min(nd, L), MAXL);   // reference scans positions < L only

    // --- Phase 1: parallel gather (collapses the dependent-load chain) ---
    if (tid < ndc) {
        const int idx = min(start + tid, NT - 1);
        int tok = draft_ids[idx];
        tok = max(0, min(tok, V - 1));
        s_tok[tid] = tok;
        s_tp[tid]  = target_probs[(size_t)idx * V + tok];
        s_dp[tid]  = draft_probs [(size_t)idx * V + tok];
        s_u[tid]   = uniform_probs[idx];
    }
    __syncthreads();

    // --- Phase 2: exact replay of the reference scan (thread 0) ---
    if (tid == 0) {
        float pi = 1.0f, U = 1.0f;
        int last = -1;
        for (int l = 0; l < ndc; ++l) {
            const float dp = s_dp[l];
            const bool  ok = (dp > 0.0f);
            const float r  = ok ? __fdiv_rn(s_tp[l], dp) : 1.0f;  // IEEE RN, fast-math-proof
            pi = fminf(__fmul_rn(pi, r), 1.0f);
            U  = __fmul_rn(U, s_u[l]);
            if (ok && pi >= U) last = l;   // scan does NOT stop at first reject
        }
        const int rej = (nd > 0) && (last != nd - 1);
        int rec = start + last + 1;
        rec = max(0, min(rec, NT - 1));
        s_last = last;
        s_rej  = rej;
        s_rec  = rec;

        float* o = out + (size_t)b * (L + 1);
        for (int c = 0; c <= L; ++c)
            o[c] = (c < L && c <= last && c < MAXL) ? (float)s_tok[c] : -1.0f;
        if (!rej)
            o[min(nd, L)] = (float)bonus[b];   // bonus token at column ndraft
    }
    __syncthreads();

    // --- Phase 3: branch-free packed-key argmax over target_probs[rec] ---
    // Softmax probs are >= 0, so their f32 bit patterns are monotone under
    // unsigned compare. key = (val_bits << 32) | ~index: u64-max == argmax with
    // exact first-occurrence tie-break (equal val -> larger ~index -> smaller index).
    if (s_rej) {
        const uint4* row4 = (const uint4*)(target_probs + (size_t)s_rec * V);
        const int n4 = V >> 2;

        // 4 independent accumulator chains (one per float4 lane) -> no serial
        // dependency across elements; loads front-batch freely.
        u64 k0 = 0, k1 = 0, k2 = 0, k3 = 0;
        #pragma unroll 4
        for (int i = tid; i < n4; i += THREADS) {
            const uint4 v = __ldg(&row4[i]);
            const u32 nb = ~(u32)(i << 2);           // ~base; ~(base+k) = nb - k
            const u64 c0 = ((u64)v.x << 32) | nb;
            const u64 c1 = ((u64)v.y << 32) | (nb - 1u);
            const u64 c2 = ((u64)v.z << 32) | (nb - 2u);
            const u64 c3 = ((u64)v.w << 32) | (nb - 3u);
            if (c0 > k0) k0 = c0;
            if (c1 > k1) k1 = c1;
            if (c2 > k2) k2 = c2;
            if (c3 > k3) k3 = c3;
        }
        // scalar tail if V % 4 != 0
        const float* rowf = (const float*)row4;
        for (int i = (n4 << 2) + tid; i < V; i += THREADS) {
            const u64 c = ((u64)__float_as_uint(rowf[i]) << 32) | ~(u32)i;
            if (c > k0) k0 = c;
        }

        u64 best = k0;
        if (k1 > best) best = k1;
        if (k2 > best) best = k2;
        if (k3 > best) best = k3;

        // warp reduction (u64 shfl lowered to 2x b32 shfl)
        #pragma unroll
        for (int off = 16; off; off >>= 1) {
            const u64 o64 = __shfl_xor_sync(0xffffffff, best, off);
            if (o64 > best) best = o64;
        }
        const int wid  = tid >> 5;
        const int lane = tid & 31;
        if (lane == 0) s_key[wid] = best;
        __syncthreads();
        if (wid == 0) {
            constexpr int NW = THREADS / 32;
            best = (lane < NW) ? s_key[lane] : 0ull;
            #pragma unroll
            for (int off = 16; off; off >>= 1) {
                const u64 o64 = __shfl_xor_sync(0xffffffff, best, off);
                if (o64 > best) best = o64;
            }
            if (lane == 0) {
                const int idx = (int)(~(u32)best);
                out[(size_t)b * (L + 1) + (s_last + 1)] = (float)idx;
            }
        }
    }
}

extern "C" void kernel_launch(void* const* d_in, const int* in_sizes, int n_in,
                              void* d_out, int out_size)
{
    // ---- order-agnostic slot resolution from sizes ----
    long long sz[6];
    for (int i = 0; i < 6; ++i) sz[i] = (i < n_in) ? (long long)in_sizes[i] : 0;

    long long mx = 0;
    for (int i = 0; i < 6; ++i) mx = (sz[i] > mx) ? sz[i] : mx;
    int ip[2], npb = 0;
    for (int i = 0; i < 6 && npb < 2; ++i) if (sz[i] == mx) ip[npb++] = i;
    if (npb < 2) ip[1] = ip[0];

    int rest[4], nr = 0;
    for (int i = 0; i < 6; ++i) if (i != ip[0] && i != ip[1] && nr < 4) rest[nr++] = i;

    long long vA = sz[rest[0]], vB = -1;
    for (int j = 1; j < 4; ++j) if (sz[rest[j]] != vA) { vB = sz[rest[j]]; break; }
    long long Bv, NTv;
    if (vB < 0) { Bv = vA; NTv = vA; }
    else {
        const bool aOK = (vA > 0) && (out_size % vA == 0) && (out_size / vA >= 2);
        const bool bOK = (vB > 0) && (out_size % vB == 0) && (out_size / vB >= 2);
        if (aOK && !bOK)      Bv = vA;
        else if (bOK && !aOK) Bv = vB;
        else                  Bv = (vA < vB) ? vA : vB;   // B <= NT (SPEC >= 1)
        NTv = (Bv == vA) ? vB : vA;
    }

    int iNT[2], iB[2]; int nnt = 0, nb = 0;
    for (int j = 0; j < 4; ++j) {
        if (sz[rest[j]] == NTv && nnt < 2)      iNT[nnt++] = rest[j];
        else if (nb < 2)                        iB[nb++]  = rest[j];
    }
    if (nnt < 2) iNT[1] = iNT[0];
    if (nb  < 1) { iB[0] = iNT[0]; iB[1] = iNT[1]; }
    else if (nb < 2) iB[1] = iB[0];

    const int NT = (int)NTv;
    const int B  = (int)Bv;
    const int V  = (int)(mx / (NTv > 0 ? NTv : 1));
    int L = (B > 0) ? (out_size / B - 1) : 4;
    if (L < 1) L = 1;

    rejection_sample_kernel<<<(B > 0 ? B : 1), THREADS>>>(
        (const float*)d_in[ip[0]], (const float*)d_in[ip[1]],
        d_in[iNT[0]], d_in[iNT[1]],
        (const int*)d_in[iB[0]], (const int*)d_in[iB[1]],
        (float*)d_out, NT, V, L, B);
}